// round 8
// baseline (speedup 1.0000x reference)
#include <cuda_runtime.h>
#include <math.h>
#include <stdint.h>

#define T_LEN 4096
#define NSIG  4096          // 16 * 256 signals
#define TOPK  7

// -------- scratch (module-scope device memory; no runtime allocation) -------
__device__ float2 d_tw[T_LEN];                  // e^{-2*pi*i*j/4096} (for recon)
__device__ int    d_pk [NSIG * TOPK];           // selected frequency index k
__device__ float  d_pre[NSIG * TOPK];           // coefficient real = 4*Re(X)/T
__device__ float  d_pim[NSIG * TOPK];           // coefficient imag = 4*Im(X)/T

// W16^e = (cos(pi*e/8), -sin(pi*e/8)), e = 0..9
__constant__ float2 W16C[10] = {
    { 1.0f, 0.0f},
    { 0.92387953251128674f, -0.38268343236508978f},
    { 0.70710678118654752f, -0.70710678118654752f},
    { 0.38268343236508978f, -0.92387953251128674f},
    { 0.0f, -1.0f},
    { 0.0f,  0.0f},   // unused
    {-0.70710678118654752f, -0.70710678118654752f},
    { 0.0f,  0.0f},   // unused
    { 0.0f,  0.0f},   // unused
    {-0.92387953251128674f,  0.38268343236508978f},
};

// ---------------------------------------------------------------------------
// complex helpers
// ---------------------------------------------------------------------------
__device__ __forceinline__ float2 cmul(float2 a, float2 b) {
    return make_float2(a.x * b.x - a.y * b.y, a.x * b.y + a.y * b.x);
}
__device__ __forceinline__ float2 cadd(float2 a, float2 b) { return make_float2(a.x + b.x, a.y + b.y); }
__device__ __forceinline__ float2 csub(float2 a, float2 b) { return make_float2(a.x - b.x, a.y - b.y); }
__device__ __forceinline__ float2 mnegi(float2 a) { return make_float2(a.y, -a.x); }  // -i * a

// In-place 16-point DFT: two radix-4 passes, NO temp array.
// After the call, Y[j] lives at slot YSLOT(j) = 4*(j&3) + (j>>2).
#define YSLOT(j) (4 * ((j) & 3) + ((j) >> 2))
__device__ __forceinline__ void dft16_ip(float2 v[16]) {
    #pragma unroll
    for (int m = 0; m < 4; m++) {
        float2 a0 = v[m], a1 = v[m + 4], a2 = v[m + 8], a3 = v[m + 12];
        float2 s02 = cadd(a0, a2), d02 = csub(a0, a2);
        float2 s13 = cadd(a1, a3), d13 = csub(a1, a3);
        float2 id  = mnegi(d13);
        v[m]      = cadd(s02, s13);
        v[m + 4]  = cadd(d02, id);
        v[m + 8]  = csub(s02, s13);
        v[m + 12] = csub(d02, id);
    }
    #pragma unroll
    for (int j1 = 1; j1 < 4; j1++)
        #pragma unroll
        for (int m = 1; m < 4; m++)
            v[m + 4 * j1] = cmul(v[m + 4 * j1], W16C[m * j1]);
    #pragma unroll
    for (int g = 0; g < 4; g++) {
        float2 a0 = v[4*g], a1 = v[4*g + 1], a2 = v[4*g + 2], a3 = v[4*g + 3];
        float2 s02 = cadd(a0, a2), d02 = csub(a0, a2);
        float2 s13 = cadd(a1, a3), d13 = csub(a1, a3);
        float2 id  = mnegi(d13);
        v[4*g]     = cadd(s02, s13);
        v[4*g + 1] = cadd(d02, id);
        v[4*g + 2] = csub(s02, s13);
        v[4*g + 3] = csub(d02, id);
    }
}

// ---------------------------------------------------------------------------
// K1: each block owns a d-QUAD (4 channels): float4 loads (16B per 32B
// sector, halves L2 amplification), two packed-real FFTs run sequentially
// (pass 0 = (x,y) pair, pass 1 = (z,w) pair stashed in smem, thread-private
// addresses so no extra barriers). Stage twiddles computed in-thread via
// sincospif (same arguments => identical values to the old table).
// Blocks 0..15 also fill d_tw for k_recon.
// Smem: sY 34816 B + stash 32768 B + 96 B scratch = 67.7 KB -> 3 blocks/SM.
// ---------------------------------------------------------------------------
__global__ void __launch_bounds__(256, 3) k_fft(const float* __restrict__ x) {
    extern __shared__ char smraw[];
    float2* sY    = (float2*)smraw;                    // 4352 float2
    float2* stash = (float2*)(smraw + 34816);          // 4096 float2
    float*  cv = (float*)(smraw + 67584);              // 8 floats
    int*    ck = (int*)  (smraw + 67616);              // 8 ints
    int*    kb = (int*)  (smraw + 67648);              // 2 ints

    int tid = threadIdx.x;
    int b   = blockIdx.x >> 6;       // 16 batches
    int q   = blockIdx.x & 63;       // d-quad: channels 4q .. 4q+3

    // side job: fill the recon twiddle table (read only by k_recon, later)
    if (blockIdx.x < 16) {
        int j = blockIdx.x * 256 + tid;
        float sp, cp;
        sincospif(-(float)j * (1.0f / 2048.0f), &sp, &cp);
        d_tw[j] = make_float2(cp, sp);
    }

    float2 v[16];

    // ---- load: 16 x float4; (x,y) kept for pass 0, (z,w) stashed ----
    {
        const float4* xp = (const float4*)x + ((size_t)b * 4096 + tid) * 64 + q;
        #pragma unroll
        for (int r = 0; r < 16; r++) {
            float4 t4 = xp[(size_t)r * 16384];       // t += 256
            v[r] = make_float2(t4.x, t4.y);
            stash[tid + 256 * r] = make_float2(t4.z, t4.w);
        }
    }

    // per-thread stage twiddles (same values as the old d_tw entries)
    float2 w1, w2;
    {
        float sp, cp;
        sincospif(-(float)tid * (1.0f / 2048.0f), &sp, &cp);
        w1 = make_float2(cp, sp);                     // e^{-2pi i tid/4096}
        sincospif(-(float)(tid & 15) * (1.0f / 128.0f), &sp, &cp);
        w2 = make_float2(cp, sp);                     // e^{-2pi i 16*(tid&15)/4096}
    }

    #pragma unroll 1
    for (int pass = 0; pass < 2; pass++) {
        if (pass) {
            #pragma unroll
            for (int r = 0; r < 16; r++) v[r] = stash[tid + 256 * r];
        }

        // ---- stage 1: a = tid ----
        dft16_ip(v);
        {
            int c = tid >> 4, bb = tid & 15;
            float2 p = w1;
            sY[c * 17 + bb] = v[YSLOT(0)];
            #pragma unroll
            for (int j = 1; j < 16; j++) {
                sY[j * 272 + c * 17 + bb] = cmul(v[YSLOT(j)], p);
                p = cmul(p, w1);
            }
        }
        __syncthreads();

        // ---- stage 2 (in place; each thread owns its address set) ----
        {
            int j = tid >> 4, bb = tid & 15;
            int base = j * 272 + bb;
            #pragma unroll
            for (int c = 0; c < 16; c++) v[c] = sY[base + c * 17];
            dft16_ip(v);
            float2 p = w2;
            sY[base] = v[YSLOT(0)];
            #pragma unroll
            for (int i = 1; i < 16; i++) {
                sY[base + i * 17] = cmul(v[YSLOT(i)], p);
                p = cmul(p, w2);
            }
        }
        __syncthreads();

        // ---- stage 3: read own set into regs, sync, scatter spectrum ----
        {
            int j = tid >> 4, i = tid & 15;
            #pragma unroll
            for (int bb = 0; bb < 16; bb++) v[bb] = sY[j * 272 + i * 17 + bb];
            dft16_ip(v);
            __syncthreads();
            // X[k], k = j+16i+256l, stored at k + (k>>4) = j + 17i + 272l
            #pragma unroll
            for (int l = 0; l < 16; l++)
                sY[j + 17 * i + 272 * l] = v[YSLOT(l)];
        }
        __syncthreads();

        // ---- top-7 on squared magnitudes, register-resident ----
        int s    = tid >> 7;
        int lid  = tid & 127;
        int wid  = tid >> 5;
        int lane = tid & 31;

        float mv[16];
        #pragma unroll
        for (int i = 0; i < 16; i++) {
            int k = 1 + lid + 128 * i;
            float m2 = -1.0f;
            if (k < 2048) {
                float2 Z1 = sY[k + (k >> 4)];
                int k2 = 4096 - k;
                float2 Z2 = sY[k2 + (k2 >> 4)];
                float xr, xi;
                if (s == 0) { xr = Z1.x + Z2.x; xi = Z1.y - Z2.y; }
                else        { xr = Z1.y + Z2.y; xi = Z2.x - Z1.x; }
                m2 = xr * xr + xi * xi;     // 4*|X|^2 (monotone in |X|)
            }
            mv[i] = m2;
        }

        float bv = -2.0f; int bk = 1 << 30;
        #pragma unroll
        for (int i = 0; i < 16; i++)
            if (mv[i] > bv) { bv = mv[i]; bk = 1 + lid + 128 * i; }

        for (int r = 0; r < TOPK; r++) {
            float rv = bv; int rk = bk;
            #pragma unroll
            for (int off = 16; off; off >>= 1) {
                float ov = __shfl_down_sync(0xffffffffu, rv, off);
                int   ok = __shfl_down_sync(0xffffffffu, rk, off);
                if (ov > rv || (ov == rv && ok < rk)) { rv = ov; rk = ok; }
            }
            if (lane == 0) { cv[wid] = rv; ck[wid] = rk; }
            __syncthreads();
            if (lid == 0) {
                float Bv = cv[s * 4]; int Bk = ck[s * 4];
                #pragma unroll
                for (int w = 1; w < 4; w++) {
                    float ov = cv[s * 4 + w]; int ok = ck[s * 4 + w];
                    if (ov > Bv || (ov == Bv && ok < Bk)) { Bv = ov; Bk = ok; }
                }
                int k = Bk;
                float2 Z1 = sY[k + (k >> 4)];
                int k2 = 4096 - k;
                float2 Z2 = sY[k2 + (k2 >> 4)];
                float Xr, Xi;
                if (s == 0) { Xr = 0.5f * (Z1.x + Z2.x); Xi = 0.5f * (Z1.y - Z2.y); }
                else        { Xr = 0.5f * (Z1.y + Z2.y); Xi = 0.5f * (Z2.x - Z1.x); }
                int sig = b * 256 + 4 * q + 2 * pass + s;
                d_pk [sig * TOPK + r] = k;
                d_pre[sig * TOPK + r] = Xr * (4.0f / 4096.0f);
                d_pim[sig * TOPK + r] = Xi * (4.0f / 4096.0f);
                kb[s] = k;                  // broadcast winner
            }
            __syncthreads();
            if (r + 1 < TOPK) {
                int rel = kb[s] - 1 - lid;
                if (rel >= 0 && rel < 2048 && (rel & 127) == 0) {
                    int slot = rel >> 7;
                    #pragma unroll
                    for (int i = 0; i < 16; i++)
                        if (i == slot) mv[i] = -1.0f;
                    bv = -2.0f; bk = 1 << 30;
                    #pragma unroll
                    for (int i = 0; i < 16; i++)
                        if (mv[i] > bv) { bv = mv[i]; bk = 1 + lid + 128 * i; }
                }
                __syncthreads();
            }
        }
        // last topk round ends with __syncthreads(): sY reads complete
        // before the next pass overwrites it.
    }
}

// ---------------------------------------------------------------------------
// K2: reconstruction via Chebyshev 3-term recurrence (step = 8 samples)
//     p_n = 2*cos(8w)*p_{n-1} - p_{n-2}, exact-table seeds.
// block = (32 d-lanes, 8 t-phases); thread strides t by 8, 128 outputs.
// ---------------------------------------------------------------------------
__global__ void __launch_bounds__(256) k_recon(float* __restrict__ out) {
    int tx = threadIdx.x, ty = threadIdx.y;
    int d   = blockIdx.x * 32 + tx;
    int b   = blockIdx.y;
    int t0  = blockIdx.z * 1024 + ty;
    int sig = b * 256 + d;

    float p0[TOPK], p1[TOPK], c2[TOPK];
    #pragma unroll
    for (int j = 0; j < TOPK; j++) {
        int   k  = d_pk [sig * TOPK + j];
        float cr = d_pre[sig * TOPK + j];
        float ci = d_pim[sig * TOPK + j];
        float2 w0 = d_tw[(k * t0) & 4095];        // (cos, -sin) of w*t0
        p0[j] = cr * w0.x + ci * w0.y;            // Re(C * e^{i w t0})
        float2 w1 = d_tw[(k * (t0 + 8)) & 4095];
        p1[j] = cr * w1.x + ci * w1.y;
        c2[j] = 2.0f * d_tw[(8 * k) & 4095].x;    // 2*cos(8w)
    }

    float* po = out + ((size_t)b * 4096 + t0) * 256 + d;
    {
        float a0 = 0.0f, a1 = 0.0f;
        #pragma unroll
        for (int j = 0; j < TOPK; j++) { a0 += p0[j]; a1 += p1[j]; }
        po[0]    = a0;
        po[2048] = a1;    // 8 * 256
    }

    #pragma unroll 4
    for (int n = 2; n < 128; n += 2) {
        float s0 = 0.0f, s1 = 0.0f;
        #pragma unroll
        for (int j = 0; j < TOPK; j++) {
            p0[j] = c2[j] * p1[j] - p0[j];
            s0 += p0[j];
        }
        po[(size_t)n * 2048] = s0;
        #pragma unroll
        for (int j = 0; j < TOPK; j++) {
            p1[j] = c2[j] * p0[j] - p1[j];
            s1 += p1[j];
        }
        po[(size_t)(n + 1) * 2048] = s1;
    }
}

// ---------------------------------------------------------------------------
extern "C" void kernel_launch(void* const* d_in, const int* in_sizes, int n_in,
                              void* d_out, int out_size) {
    (void)in_sizes; (void)n_in; (void)out_size;
    const float* x = (const float*)d_in[0];
    float* out = (float*)d_out;

    cudaFuncSetAttribute(k_fft, cudaFuncAttributeMaxDynamicSharedMemorySize, 67712);

    k_fft<<<1024, 256, 67712>>>(x);

    dim3 gr(8, 16, 4), br(32, 8);
    k_recon<<<gr, br>>>(out);
}

// round 9
// speedup vs baseline: 1.2786x; 1.2786x over previous
#include <cuda_runtime.h>
#include <math.h>
#include <stdint.h>

#define T_LEN 4096
#define NSIG  4096          // 16 * 256 signals
#define TOPK  7

// -------- scratch (module-scope device memory; no runtime allocation) -------
__device__ float2 d_tw[T_LEN];                  // e^{-2*pi*i*j/4096} (for recon)
__device__ int    d_pk [NSIG * TOPK];           // selected frequency index k
__device__ float  d_pre[NSIG * TOPK];           // coefficient real = 4*Re(X)/T
__device__ float  d_pim[NSIG * TOPK];           // coefficient imag = 4*Im(X)/T

// W16^e = (cos(pi*e/8), -sin(pi*e/8)), e = 0..9
__constant__ float2 W16C[10] = {
    { 1.0f, 0.0f},
    { 0.92387953251128674f, -0.38268343236508978f},
    { 0.70710678118654752f, -0.70710678118654752f},
    { 0.38268343236508978f, -0.92387953251128674f},
    { 0.0f, -1.0f},
    { 0.0f,  0.0f},   // unused
    {-0.70710678118654752f, -0.70710678118654752f},
    { 0.0f,  0.0f},   // unused
    { 0.0f,  0.0f},   // unused
    {-0.92387953251128674f,  0.38268343236508978f},
};

// ---------------------------------------------------------------------------
// complex helpers
// ---------------------------------------------------------------------------
__device__ __forceinline__ float2 cmul(float2 a, float2 b) {
    return make_float2(a.x * b.x - a.y * b.y, a.x * b.y + a.y * b.x);
}
__device__ __forceinline__ float2 cadd(float2 a, float2 b) { return make_float2(a.x + b.x, a.y + b.y); }
__device__ __forceinline__ float2 csub(float2 a, float2 b) { return make_float2(a.x - b.x, a.y - b.y); }
__device__ __forceinline__ float2 mnegi(float2 a) { return make_float2(a.y, -a.x); }  // -i * a

// In-place 16-point DFT: two radix-4 passes, NO temp array.
// After the call, Y[j] lives at slot YSLOT(j) = 4*(j&3) + (j>>2).
#define YSLOT(j) (4 * ((j) & 3) + ((j) >> 2))
__device__ __forceinline__ void dft16_ip(float2 v[16]) {
    #pragma unroll
    for (int m = 0; m < 4; m++) {
        float2 a0 = v[m], a1 = v[m + 4], a2 = v[m + 8], a3 = v[m + 12];
        float2 s02 = cadd(a0, a2), d02 = csub(a0, a2);
        float2 s13 = cadd(a1, a3), d13 = csub(a1, a3);
        float2 id  = mnegi(d13);
        v[m]      = cadd(s02, s13);
        v[m + 4]  = cadd(d02, id);
        v[m + 8]  = csub(s02, s13);
        v[m + 12] = csub(d02, id);
    }
    #pragma unroll
    for (int j1 = 1; j1 < 4; j1++)
        #pragma unroll
        for (int m = 1; m < 4; m++)
            v[m + 4 * j1] = cmul(v[m + 4 * j1], W16C[m * j1]);
    #pragma unroll
    for (int g = 0; g < 4; g++) {
        float2 a0 = v[4*g], a1 = v[4*g + 1], a2 = v[4*g + 2], a3 = v[4*g + 3];
        float2 s02 = cadd(a0, a2), d02 = csub(a0, a2);
        float2 s13 = cadd(a1, a3), d13 = csub(a1, a3);
        float2 id  = mnegi(d13);
        v[4*g]     = cadd(s02, s13);
        v[4*g + 1] = cadd(d02, id);
        v[4*g + 2] = csub(s02, s13);
        v[4*g + 3] = csub(d02, id);
    }
}

// ---------------------------------------------------------------------------
// K1: 512 threads = TWO independent 256-thread halves running concurrently.
// Block owns a d-QUAD; half h processes the packed pair (4q+2h, 4q+2h+1).
// float4 loads (16B of each 32B sector -> half the L2 amplification of the
// d-pair version); each thread loads 8 rows and routes (x,y) / (z,w) to the
// respective half's smem staging. Both halves execute identical barrier
// sequences, so whole-block __syncthreads stays valid.
// Smem: 2 x 4352 float2 (69632 B) + 160 B scratch -> 2 blocks/SM, 32 warps.
// ---------------------------------------------------------------------------
__global__ void __launch_bounds__(512, 2) k_fft(const float* __restrict__ x) {
    extern __shared__ char smraw[];
    float2* sYall = (float2*)smraw;              // 2 x 4352 float2
    float*  cv = (float*)(smraw + 69632);        // 16 floats
    int*    ck = (int*)  (smraw + 69632 + 64);   // 16 ints
    int*    kb = (int*)  (smraw + 69632 + 128);  // 4 ints

    int tid = threadIdx.x;
    int h   = tid >> 8;              // half: 0 or 1
    int t   = tid & 255;             // thread-in-half
    int b   = blockIdx.x >> 6;       // 16 batches
    int q   = blockIdx.x & 63;       // d-quad: channels 4q .. 4q+3

    float2* sY  = sYall + h * 4352;  // this half's buffer
    float2* sYA = sYall;             // half-0 staging
    float2* sYB = sYall + 4352;      // half-1 staging

    // side job: fill the recon twiddle table (blocks 0..7)
    if (blockIdx.x < 8) {
        int j = blockIdx.x * 512 + tid;
        float sp, cp;
        sincospif(-(float)j * (1.0f / 2048.0f), &sp, &cp);
        d_tw[j] = make_float2(cp, sp);
    }

    // ---- cooperative load: thread (h,t) loads rows 8h..8h+7 at time t ----
    // staging layout: value (time=t, row) at sY_half[row*257 + t]
    {
        const float4* xp = (const float4*)x + ((size_t)b * 4096 + t) * 64 + q;
        #pragma unroll
        for (int r = 0; r < 8; r++) {
            int row = 8 * h + r;
            float4 t4 = xp[(size_t)row * 16384];     // time t + 256*row
            sYA[row * 257 + t] = make_float2(t4.x, t4.y);
            sYB[row * 257 + t] = make_float2(t4.z, t4.w);
        }
    }

    // per-thread stage twiddles
    float2 w1, w2;
    {
        float sp, cp;
        sincospif(-(float)t * (1.0f / 2048.0f), &sp, &cp);
        w1 = make_float2(cp, sp);                 // e^{-2pi i t/4096}
        sincospif(-(float)(t & 15) * (1.0f / 128.0f), &sp, &cp);
        w2 = make_float2(cp, sp);                 // e^{-2pi i 16*(t&15)/4096}
    }
    __syncthreads();

    float2 v[16];

    // ---- stage 1: gather own time-column from staging, then butterfly ----
    {
        #pragma unroll
        for (int row = 0; row < 16; row++) v[row] = sY[row * 257 + t];
    }
    __syncthreads();     // all staging reads done before overwrite
    {
        dft16_ip(v);
        int c = t >> 4, bb = t & 15;
        float2 p = w1;
        sY[c * 17 + bb] = v[YSLOT(0)];
        #pragma unroll
        for (int j = 1; j < 16; j++) {
            sY[j * 272 + c * 17 + bb] = cmul(v[YSLOT(j)], p);
            p = cmul(p, w1);
        }
    }
    __syncthreads();

    // ---- stage 2 (in place; each thread owns its address set) ----
    {
        int j = t >> 4, bb = t & 15;
        int base = j * 272 + bb;
        #pragma unroll
        for (int c = 0; c < 16; c++) v[c] = sY[base + c * 17];
        dft16_ip(v);
        float2 p = w2;
        sY[base] = v[YSLOT(0)];
        #pragma unroll
        for (int i = 1; i < 16; i++) {
            sY[base + i * 17] = cmul(v[YSLOT(i)], p);
            p = cmul(p, w2);
        }
    }
    __syncthreads();

    // ---- stage 3: read own set into regs, sync, scatter spectrum ----
    {
        int j = t >> 4, i = t & 15;
        #pragma unroll
        for (int bb = 0; bb < 16; bb++) v[bb] = sY[j * 272 + i * 17 + bb];
        dft16_ip(v);
        __syncthreads();
        // X[k], k = j+16i+256l, stored at k + (k>>4) = j + 17i + 272l
        #pragma unroll
        for (int l = 0; l < 16; l++)
            sY[j + 17 * i + 272 * l] = v[YSLOT(l)];
    }
    __syncthreads();

    // ---- top-7 on squared magnitudes, register-resident ----
    // within a half: warps 0-3 -> signal 0, warps 4-7 -> signal 1
    int s    = t >> 7;
    int lid  = t & 127;
    int gwid = tid >> 5;             // global warp id 0..15
    int lane = tid & 31;

    float mv[16];
    #pragma unroll
    for (int i = 0; i < 16; i++) {
        int k = 1 + lid + 128 * i;
        float m2 = -1.0f;
        if (k < 2048) {
            float2 Z1 = sY[k + (k >> 4)];
            int k2 = 4096 - k;
            float2 Z2 = sY[k2 + (k2 >> 4)];
            float xr, xi;
            if (s == 0) { xr = Z1.x + Z2.x; xi = Z1.y - Z2.y; }
            else        { xr = Z1.y + Z2.y; xi = Z2.x - Z1.x; }
            m2 = xr * xr + xi * xi;     // 4*|X|^2 (monotone in |X|)
        }
        mv[i] = m2;
    }

    float bv = -2.0f; int bk = 1 << 30;
    #pragma unroll
    for (int i = 0; i < 16; i++)
        if (mv[i] > bv) { bv = mv[i]; bk = 1 + lid + 128 * i; }

    for (int r = 0; r < TOPK; r++) {
        float rv = bv; int rk = bk;
        #pragma unroll
        for (int off = 16; off; off >>= 1) {
            float ov = __shfl_down_sync(0xffffffffu, rv, off);
            int   ok = __shfl_down_sync(0xffffffffu, rk, off);
            if (ov > rv || (ov == rv && ok < rk)) { rv = ov; rk = ok; }
        }
        if (lane == 0) { cv[gwid] = rv; ck[gwid] = rk; }
        __syncthreads();
        if (lid == 0) {
            int base = h * 8 + s * 4;
            float Bv = cv[base]; int Bk = ck[base];
            #pragma unroll
            for (int w = 1; w < 4; w++) {
                float ov = cv[base + w]; int ok = ck[base + w];
                if (ov > Bv || (ov == Bv && ok < Bk)) { Bv = ov; Bk = ok; }
            }
            int k = Bk;
            float2 Z1 = sY[k + (k >> 4)];
            int k2 = 4096 - k;
            float2 Z2 = sY[k2 + (k2 >> 4)];
            float Xr, Xi;
            if (s == 0) { Xr = 0.5f * (Z1.x + Z2.x); Xi = 0.5f * (Z1.y - Z2.y); }
            else        { Xr = 0.5f * (Z1.y + Z2.y); Xi = 0.5f * (Z2.x - Z1.x); }
            int sig = b * 256 + 4 * q + 2 * h + s;
            d_pk [sig * TOPK + r] = k;
            d_pre[sig * TOPK + r] = Xr * (4.0f / 4096.0f);
            d_pim[sig * TOPK + r] = Xi * (4.0f / 4096.0f);
            kb[h * 2 + s] = k;          // broadcast winner
        }
        __syncthreads();
        if (r + 1 < TOPK) {
            int rel = kb[h * 2 + s] - 1 - lid;
            if (rel >= 0 && rel < 2048 && (rel & 127) == 0) {
                int slot = rel >> 7;
                #pragma unroll
                for (int i = 0; i < 16; i++)
                    if (i == slot) mv[i] = -1.0f;
                bv = -2.0f; bk = 1 << 30;
                #pragma unroll
                for (int i = 0; i < 16; i++)
                    if (mv[i] > bv) { bv = mv[i]; bk = 1 + lid + 128 * i; }
            }
            __syncthreads();
        }
    }
}

// ---------------------------------------------------------------------------
// K2: reconstruction via Chebyshev 3-term recurrence (step = 8 samples)
//     p_n = 2*cos(8w)*p_{n-1} - p_{n-2}, exact-table seeds.
// block = (32 d-lanes, 8 t-phases); thread strides t by 8, 128 outputs.
// ---------------------------------------------------------------------------
__global__ void __launch_bounds__(256) k_recon(float* __restrict__ out) {
    int tx = threadIdx.x, ty = threadIdx.y;
    int d   = blockIdx.x * 32 + tx;
    int b   = blockIdx.y;
    int t0  = blockIdx.z * 1024 + ty;
    int sig = b * 256 + d;

    float p0[TOPK], p1[TOPK], c2[TOPK];
    #pragma unroll
    for (int j = 0; j < TOPK; j++) {
        int   k  = d_pk [sig * TOPK + j];
        float cr = d_pre[sig * TOPK + j];
        float ci = d_pim[sig * TOPK + j];
        float2 w0 = d_tw[(k * t0) & 4095];        // (cos, -sin) of w*t0
        p0[j] = cr * w0.x + ci * w0.y;            // Re(C * e^{i w t0})
        float2 w1 = d_tw[(k * (t0 + 8)) & 4095];
        p1[j] = cr * w1.x + ci * w1.y;
        c2[j] = 2.0f * d_tw[(8 * k) & 4095].x;    // 2*cos(8w)
    }

    float* po = out + ((size_t)b * 4096 + t0) * 256 + d;
    {
        float a0 = 0.0f, a1 = 0.0f;
        #pragma unroll
        for (int j = 0; j < TOPK; j++) { a0 += p0[j]; a1 += p1[j]; }
        po[0]    = a0;
        po[2048] = a1;    // 8 * 256
    }

    #pragma unroll 4
    for (int n = 2; n < 128; n += 2) {
        float s0 = 0.0f, s1 = 0.0f;
        #pragma unroll
        for (int j = 0; j < TOPK; j++) {
            p0[j] = c2[j] * p1[j] - p0[j];
            s0 += p0[j];
        }
        po[(size_t)n * 2048] = s0;
        #pragma unroll
        for (int j = 0; j < TOPK; j++) {
            p1[j] = c2[j] * p0[j] - p1[j];
            s1 += p1[j];
        }
        po[(size_t)(n + 1) * 2048] = s1;
    }
}

// ---------------------------------------------------------------------------
extern "C" void kernel_launch(void* const* d_in, const int* in_sizes, int n_in,
                              void* d_out, int out_size) {
    (void)in_sizes; (void)n_in; (void)out_size;
    const float* x = (const float*)d_in[0];
    float* out = (float*)d_out;

    cudaFuncSetAttribute(k_fft, cudaFuncAttributeMaxDynamicSharedMemorySize, 69792);

    k_fft<<<1024, 512, 69792>>>(x);

    dim3 gr(8, 16, 4), br(32, 8);
    k_recon<<<gr, br>>>(out);
}